// round 14
// baseline (speedup 1.0000x reference)
#include <cuda_runtime.h>
#include <cuda_fp16.h>
#include <math.h>

#define BATCH        2048
#define IN_DIM       4096
#define OUT_DIM      1024
#define N_EDGES_MAX  16384

#define BT           256    // batch-tile (8 halves per lane per LDG.128)
#define TPB          2      // batch-tiles per block (sequential phases)
#define NPB          8      // nodes (warps) per block

// Scratch (no allocations allowed): fp16 transposed x + CSR meta.
__device__ __half g_xt[(size_t)IN_DIM * BATCH];  // 16 MB, x_t[s][b] (L2-resident)
__device__ int    g_offs[OUT_DIM + 1];
__device__ int2   g_edges[N_EDGES_MAX];          // (src, weight_bits)

// ---------------- Fused transpose(+fp16 convert) + prologue ----------------
__global__ __launch_bounds__(256)
void transpose_prologue_kernel(const float* __restrict__ x,
                               const int* __restrict__ edge_src,
                               const float* __restrict__ weights,
                               const int* __restrict__ edge_dst,
                               int n_edges) {
    const int tx = threadIdx.x, ty = threadIdx.y;

    // ---- Embedded prologue (64 blocks x 256 threads = 16384 lanes) ----
    if (blockIdx.y == 0 && blockIdx.x < 64) {
        const int i = blockIdx.x * 256 + ty * 32 + tx;
        if (i < n_edges) {
            g_edges[i] = make_int2(edge_src[i], __float_as_int(weights[i]));
            const int d  = edge_dst[i];
            const int dp = (i == 0) ? -1 : edge_dst[i - 1];
            for (int o = dp + 1; o <= d; o++) g_offs[o] = i;
            if (i == n_edges - 1)
                for (int o = d + 1; o <= OUT_DIM; o++) g_offs[o] = n_edges;
        }
    }

    // ---- Transpose tile, storing fp16 ----
    __shared__ float tile[32][33];
    const int c0 = blockIdx.x * 32;   // IN_DIM tile base
    const int b0 = blockIdx.y * 32;   // BATCH tile base
    #pragma unroll
    for (int i = 0; i < 4; i++)
        tile[ty + i * 8][tx] = x[(size_t)(b0 + ty + i * 8) * IN_DIM + c0 + tx];
    __syncthreads();
    #pragma unroll
    for (int i = 0; i < 4; i++)
        g_xt[(size_t)(c0 + ty + i * 8) * BATCH + b0 + tx] =
            __float2half(tile[tx][ty + i * 8]);
}

// ---------------- Gather ----------------
// Fast tanh -> sigmoid: tanh(v) = 1 - 2/(e^{2v}+1); sigmoid via __expf.
// Saturates correctly at +-inf; error ~1e-6 (well under fp16 noise floor).
__device__ __forceinline__ float act(float v) {
    float e  = __expf(2.0f * v);
    float th = 1.0f - __fdividef(2.0f, e + 1.0f);
    return __fdividef(1.0f, 1.0f + __expf(-th));
}

// Accumulate 8 fp16 values (one LDG.128 worth) into 8 fp32 accumulators.
__device__ __forceinline__ void acc8(float4 v, float w, float* a) {
    const __half2* h = reinterpret_cast<const __half2*>(&v);
    #pragma unroll
    for (int j = 0; j < 4; j++) {
        float2 f = __half22float2(h[j]);
        a[2 * j + 0] = fmaf(f.x, w, a[2 * j + 0]);
        a[2 * j + 1] = fmaf(f.y, w, a[2 * j + 1]);
    }
}

#define SHFL_SW(k) \
    int   s##k = __shfl_sync(0xFFFFFFFFu, ep.x, i + k); \
    float w##k = __int_as_float(__shfl_sync(0xFFFFFFFFu, ep.y, i + k));

__global__ __launch_bounds__(NPB * 32, 4)   // <=64 regs, 4 blocks/SM, 1 wave
void gather_kernel(float* __restrict__ out) {
    __shared__ float t[BT][NPB + 1];

    const int warp = threadIdx.x >> 5;
    const int lane = threadIdx.x & 31;
    const int o    = blockIdx.y * NPB + warp;          // node (warp-uniform)

    const float4* __restrict__ xt4 = reinterpret_cast<const float4*>(g_xt);
    const int beg = g_offs[o];
    const int cnt = g_offs[o + 1] - beg;

    for (int tile = 0; tile < TPB; tile++) {
        const int bt = blockIdx.x * TPB + tile;        // batch-tile index
        const int bq = bt * 32 + lane;                 // float4 index in row

        float a[8];
        #pragma unroll
        for (int j = 0; j < 8; j++) a[j] = 0.0f;

        // Warp-cooperative edge fetch (1 LDG.64 per 32 edges) + shfl
        // broadcast. Unroll x8: 8 independent LDG.128 in flight per warp.
        for (int base = 0; base < cnt; base += 32) {
            const int rem = min(32, cnt - base);
            int2 ep = make_int2(0, 0);
            if (lane < rem) ep = __ldg(&g_edges[beg + base + lane]);

            int i = 0;
            for (; i + 7 < rem; i += 8) {
                SHFL_SW(0) SHFL_SW(1) SHFL_SW(2) SHFL_SW(3)
                SHFL_SW(4) SHFL_SW(5) SHFL_SW(6) SHFL_SW(7)
                float4 v0 = xt4[(size_t)s0 * (BATCH / 8) + bq];
                float4 v1 = xt4[(size_t)s1 * (BATCH / 8) + bq];
                float4 v2 = xt4[(size_t)s2 * (BATCH / 8) + bq];
                float4 v3 = xt4[(size_t)s3 * (BATCH / 8) + bq];
                float4 v4 = xt4[(size_t)s4 * (BATCH / 8) + bq];
                float4 v5 = xt4[(size_t)s5 * (BATCH / 8) + bq];
                float4 v6 = xt4[(size_t)s6 * (BATCH / 8) + bq];
                float4 v7 = xt4[(size_t)s7 * (BATCH / 8) + bq];
                acc8(v0, w0, a); acc8(v1, w1, a);
                acc8(v2, w2, a); acc8(v3, w3, a);
                acc8(v4, w4, a); acc8(v5, w5, a);
                acc8(v6, w6, a); acc8(v7, w7, a);
            }
            for (; i < rem; i++) {
                int   s = __shfl_sync(0xFFFFFFFFu, ep.x, i);
                float w = __int_as_float(__shfl_sync(0xFFFFFFFFu, ep.y, i));
                acc8(xt4[(size_t)s * (BATCH / 8) + bq], w, a);
            }
        }

        // Activations (cheap EX2-based)
        #pragma unroll
        for (int j = 0; j < 8; j++) a[j] = act(a[j]);

        // smem transpose for coalesced stores
        if (tile > 0) __syncthreads();   // protect t from previous phase
        {
            const int b = lane * 8;
            #pragma unroll
            for (int j = 0; j < 8; j++) t[b + j][warp] = a[j];
        }
        __syncthreads();

        // Thread i stores batch row (bt*BT + i): 8 contiguous floats
        {
            const int i = threadIdx.x;             // 0..255
            const int b = bt * BT + i;
            float4 s0v = make_float4(t[i][0], t[i][1], t[i][2], t[i][3]);
            float4 s1v = make_float4(t[i][4], t[i][5], t[i][6], t[i][7]);
            float4* dst = reinterpret_cast<float4*>(out + (size_t)b * OUT_DIM
                                                    + blockIdx.y * NPB);
            dst[0] = s0v;
            dst[1] = s1v;
        }
    }
}

extern "C" void kernel_launch(void* const* d_in, const int* in_sizes, int n_in,
                              void* d_out, int out_size) {
    const float* x        = (const float*)d_in[0];   // [2048, 4096] f32
    const float* weights  = (const float*)d_in[1];   // [16384] f32
    const int*   edge_src = (const int*)d_in[2];     // [16384] i32
    const int*   edge_dst = (const int*)d_in[3];     // [16384] i32 (sorted)
    float*       out      = (float*)d_out;           // [2048, 1024] f32

    const int n_edges = in_sizes[1];

    // 1) Fused transpose+fp16-convert + CSR-meta build
    transpose_prologue_kernel<<<dim3(IN_DIM / 32, BATCH / 32), dim3(32, 8)>>>(
        x, edge_src, weights, edge_dst, n_edges);

    // 2) Gather: 512 blocks (2 batch-tiles each), 4 blocks/SM, single wave
    gather_kernel<<<dim3(BATCH / (BT * TPB), OUT_DIM / NPB), NPB * 32>>>(out);
}

// round 15
// speedup vs baseline: 1.0753x; 1.0753x over previous
#include <cuda_runtime.h>
#include <cuda_fp16.h>
#include <math.h>

#define BATCH        2048
#define IN_DIM       4096
#define OUT_DIM      1024
#define N_EDGES_MAX  16384

#define BT           256    // batch-tile (8 halves per lane per LDG.128)
#define TPB          2      // batch-tiles per block (sequential phases)
#define NPB          8      // nodes (warps) per block
#define EDGE_CAP     512    // smem edge staging capacity (guarded)

// Scratch (no allocations allowed): fp16 transposed x + CSR meta.
__device__ __half g_xt[(size_t)IN_DIM * BATCH];  // 16 MB, x_t[s][b] (L2-resident)
__device__ int    g_offs[OUT_DIM + 1];
__device__ int2   g_edges[N_EDGES_MAX];          // (src, weight_bits)

// ---------------- Fused transpose(+fp16 convert) + prologue ----------------
__global__ __launch_bounds__(256)
void transpose_prologue_kernel(const float* __restrict__ x,
                               const int* __restrict__ edge_src,
                               const float* __restrict__ weights,
                               const int* __restrict__ edge_dst,
                               int n_edges) {
    const int tid = threadIdx.y * 32 + threadIdx.x;
    const int tx = threadIdx.x, ty = threadIdx.y;

    // ---- Embedded prologue (64 blocks x 256 threads = 16384 lanes) ----
    if (blockIdx.y == 0 && blockIdx.x < 64) {
        const int i = blockIdx.x * 256 + tid;
        if (i < n_edges) {
            g_edges[i] = make_int2(edge_src[i], __float_as_int(weights[i]));
            const int d  = edge_dst[i];
            const int dp = (i == 0) ? -1 : edge_dst[i - 1];
            for (int o = dp + 1; o <= d; o++) g_offs[o] = i;
            if (i == n_edges - 1)
                for (int o = d + 1; o <= OUT_DIM; o++) g_offs[o] = n_edges;
        }
    }

    // ---- Transpose tile: coalesced fp32 reads, packed 8-byte fp16 stores ----
    __shared__ float tile[32][33];              // tile[b_local][c_local]
    const int c0 = blockIdx.x * 32;             // IN_DIM tile base
    const int b0 = blockIdx.y * 32;             // BATCH tile base
    #pragma unroll
    for (int i = 0; i < 4; i++)
        tile[ty + i * 8][tx] = x[(size_t)(b0 + ty + i * 8) * IN_DIM + c0 + tx];
    __syncthreads();

    // Write: thread -> (c_local = tid>>3, 4 consecutive b at (tid&7)*4),
    // packed as 4 halves = one 8-byte store. Column reads are conflict-free
    // (stride-33 tile).
    {
        const int c_local = tid >> 3;
        const int g       = (tid & 7) * 4;
        __half h[4];
        #pragma unroll
        for (int k = 0; k < 4; k++)
            h[k] = __float2half(tile[g + k][c_local]);
        *reinterpret_cast<uint2*>(&g_xt[(size_t)(c0 + c_local) * BATCH + b0 + g])
            = *reinterpret_cast<uint2*>(h);
    }
}

// ---------------- Gather: warp-per-node, half2 accumulate ----------------
__device__ __forceinline__ float act(float v) {
    float e  = __expf(2.0f * v);
    float th = 1.0f - __fdividef(2.0f, e + 1.0f);
    return __fdividef(1.0f, 1.0f + __expf(-th));
}

// acc[0..3] (half2) += v (4x half2) * w2 (splat) -- 4 HFMA2 per edge.
__device__ __forceinline__ void acc_h2(float4 v, __half2 w2, __half2* a) {
    const __half2* h = reinterpret_cast<const __half2*>(&v);
    #pragma unroll
    for (int j = 0; j < 4; j++) a[j] = __hfma2(h[j], w2, a[j]);
}

__global__ __launch_bounds__(NPB * 32, 4)   // <=64 regs, 4 blocks/SM, 1 wave
void gather_kernel(float* __restrict__ out) {
    __shared__ int2  se[EDGE_CAP];
    __shared__ float t[BT][NPB + 1];

    const int warp = threadIdx.x >> 5;
    const int lane = threadIdx.x & 31;
    const int o    = blockIdx.y * NPB + warp;          // node (warp-uniform)

    const float4* __restrict__ xt4 = reinterpret_cast<const float4*>(g_xt);

    // ---- Stage this block's contiguous edge range once (reused by tiles) ----
    const int e_lo = g_offs[blockIdx.y * NPB];
    const int e_hi = g_offs[blockIdx.y * NPB + NPB];
    const int tot  = e_hi - e_lo;
    const int2* ebase;
    if (tot <= EDGE_CAP) {
        for (int i = threadIdx.x; i < tot; i += NPB * 32)
            se[i] = __ldg(&g_edges[e_lo + i]);
        ebase = se - e_lo;                     // index by global edge id
    } else {
        ebase = g_edges;                       // gmem fallback
    }
    __syncthreads();

    const int beg = g_offs[o];
    const int end = g_offs[o + 1];

    for (int tile = 0; tile < TPB; tile++) {
        const int bt = blockIdx.x * TPB + tile;        // batch-tile index
        const int bq = bt * 32 + lane;                 // float4 index in row

        __half2 a[4];
        #pragma unroll
        for (int j = 0; j < 4; j++) a[j] = __half2half2(__ushort_as_half(0));

        // Edge loop: broadcast LDS edge reads, 8 independent LDG.128 in flight.
        int e = beg;
        for (; e + 7 < end; e += 8) {
            int2 p0 = ebase[e + 0];  int2 p1 = ebase[e + 1];
            int2 p2 = ebase[e + 2];  int2 p3 = ebase[e + 3];
            int2 p4 = ebase[e + 4];  int2 p5 = ebase[e + 5];
            int2 p6 = ebase[e + 6];  int2 p7 = ebase[e + 7];
            float4 v0 = xt4[(size_t)p0.x * (BATCH / 8) + bq];
            float4 v1 = xt4[(size_t)p1.x * (BATCH / 8) + bq];
            float4 v2 = xt4[(size_t)p2.x * (BATCH / 8) + bq];
            float4 v3 = xt4[(size_t)p3.x * (BATCH / 8) + bq];
            float4 v4 = xt4[(size_t)p4.x * (BATCH / 8) + bq];
            float4 v5 = xt4[(size_t)p5.x * (BATCH / 8) + bq];
            float4 v6 = xt4[(size_t)p6.x * (BATCH / 8) + bq];
            float4 v7 = xt4[(size_t)p7.x * (BATCH / 8) + bq];
            acc_h2(v0, __float2half2_rn(__int_as_float(p0.y)), a);
            acc_h2(v1, __float2half2_rn(__int_as_float(p1.y)), a);
            acc_h2(v2, __float2half2_rn(__int_as_float(p2.y)), a);
            acc_h2(v3, __float2half2_rn(__int_as_float(p3.y)), a);
            acc_h2(v4, __float2half2_rn(__int_as_float(p4.y)), a);
            acc_h2(v5, __float2half2_rn(__int_as_float(p5.y)), a);
            acc_h2(v6, __float2half2_rn(__int_as_float(p6.y)), a);
            acc_h2(v7, __float2half2_rn(__int_as_float(p7.y)), a);
        }
        for (; e < end; e++) {
            int2 p = ebase[e];
            acc_h2(xt4[(size_t)p.x * (BATCH / 8) + bq],
                   __float2half2_rn(__int_as_float(p.y)), a);
        }

        // Activations (fp32 epilogue)
        float f[8];
        #pragma unroll
        for (int j = 0; j < 4; j++) {
            float2 fv = __half22float2(a[j]);
            f[2 * j + 0] = act(fv.x);
            f[2 * j + 1] = act(fv.y);
        }

        // smem transpose for coalesced stores
        __syncthreads();                        // protects se (tile 0) / t
        {
            const int b = lane * 8;
            #pragma unroll
            for (int j = 0; j < 8; j++) t[b + j][warp] = f[j];
        }
        __syncthreads();

        // Thread i stores batch row (bt*BT + i): 8 contiguous floats
        {
            const int i = threadIdx.x;             // 0..255
            const int b = bt * BT + i;
            float4 s0v = make_float4(t[i][0], t[i][1], t[i][2], t[i][3]);
            float4 s1v = make_float4(t[i][4], t[i][5], t[i][6], t[i][7]);
            float4* dst = reinterpret_cast<float4*>(out + (size_t)b * OUT_DIM
                                                    + blockIdx.y * NPB);
            dst[0] = s0v;
            dst[1] = s1v;
        }
    }
}

extern "C" void kernel_launch(void* const* d_in, const int* in_sizes, int n_in,
                              void* d_out, int out_size) {
    const float* x        = (const float*)d_in[0];   // [2048, 4096] f32
    const float* weights  = (const float*)d_in[1];   // [16384] f32
    const int*   edge_src = (const int*)d_in[2];     // [16384] i32
    const int*   edge_dst = (const int*)d_in[3];     // [16384] i32 (sorted)
    float*       out      = (float*)d_out;           // [2048, 1024] f32

    const int n_edges = in_sizes[1];

    // 1) Fused transpose+fp16-convert + CSR-meta build
    transpose_prologue_kernel<<<dim3(IN_DIM / 32, BATCH / 32), dim3(32, 8)>>>(
        x, edge_src, weights, edge_dst, n_edges);

    // 2) Gather: 512 blocks (2 batch-tiles each), 4 blocks/SM, single wave
    gather_kernel<<<dim3(BATCH / (BT * TPB), OUT_DIM / NPB), NPB * 32>>>(out);
}